// round 13
// baseline (speedup 1.0000x reference)
#include <cuda_runtime.h>
#include <cuda_fp16.h>
#include <cstdint>
#include <math.h>

// ---------------------------------------------------------------------------
// Problem constants
// ---------------------------------------------------------------------------
#define NNODES 8192
#define FDIM   16
#define HDIM   64
#define GSEG   256
#define LNEPS  1e-3f
#define ASCALE 8192.0f
#define AINV   (1.0f / 8192.0f)

// Hybrid GEMM: A f32 via LDG->cvt->STS(fp16), B fp16 via cp.async
#define BM 128
#define NSPLIT 8
#define KSPLIT (NNODES / NSPLIT)   // 1024
#define BKH 32                     // k-elements per tile
#define NITH (KSPLIT / BKH)        // 32
#define LDH 72                     // half pitch (144 B) -- proven conflict-free
#define STAH (BM * LDH * 2)        // 18432 B per A stage
#define STBH (64 * LDH * 2)        // 9216 B per B stage
#define NSTB 4                     // B cp.async stages
#define SMEMG (2 * STAH + NSTB * STBH)  // 73728 B

// ---------------------------------------------------------------------------
// Device scratch
// ---------------------------------------------------------------------------
__device__ __half dY0Th[HDIM * NNODES];           // (X@W0)^T fp16
__device__ __half dY1Th[HDIM * NNODES];           // (h0@W1)^T fp16
__device__ float dZP[NSPLIT * NNODES * HDIM];     // split-K partials
__device__ float dH0[NNODES * HDIM];
__device__ float dG[GSEG * HDIM];
__device__ float dZsum[GSEG];
__device__ float dZnum[GSEG * 3];

// ---------------------------------------------------------------------------
// PTX helpers
// ---------------------------------------------------------------------------
__device__ __forceinline__ void cpa16(uint32_t dst, const void *src) {
    asm volatile("cp.async.cg.shared.global [%0], [%1], 16;" ::"r"(dst), "l"(src));
}
__device__ __forceinline__ void cpa_commit() {
    asm volatile("cp.async.commit_group;");
}
__device__ __forceinline__ void ldsm4(uint32_t &r0, uint32_t &r1, uint32_t &r2,
                                      uint32_t &r3, uint32_t addr) {
    asm volatile("ldmatrix.sync.aligned.m8n8.x4.shared.b16 {%0,%1,%2,%3}, [%4];"
                 : "=r"(r0), "=r"(r1), "=r"(r2), "=r"(r3) : "r"(addr));
}
__device__ __forceinline__ void mma_f16(float c[4], const uint32_t a[4],
                                        const uint32_t b[2]) {
    asm volatile(
        "mma.sync.aligned.m16n8k16.row.col.f32.f16.f16.f32 "
        "{%0,%1,%2,%3}, {%4,%5,%6,%7}, {%8,%9}, {%0,%1,%2,%3};"
        : "+f"(c[0]), "+f"(c[1]), "+f"(c[2]), "+f"(c[3])
        : "r"(a[0]), "r"(a[1]), "r"(a[2]), "r"(a[3]), "r"(b[0]), "r"(b[1]));
}

// ---------------------------------------------------------------------------
// initg: zero dG (also the launch spacer so gemm1 is 4th for ncu)
// ---------------------------------------------------------------------------
__global__ void initg_kernel() {
    int i = blockIdx.x * 256 + threadIdx.x;
    if (i < GSEG * HDIM) dG[i] = 0.f;
}

// ---------------------------------------------------------------------------
// y0t: Y0Th[n][i] = fp16(sum_f X[i][f]*W0[f][n])
// ---------------------------------------------------------------------------
__global__ void y0t_kernel(const float *__restrict__ X, const float *__restrict__ W0) {
    __shared__ float W0s[FDIM][HDIM];
    __shared__ float ybuf[8][68];
    int lane = threadIdx.x, ty = threadIdx.y;
    int tid = ty * 32 + lane;
#pragma unroll
    for (int j = 0; j < 4; j++) {
        int idx = tid + 256 * j;
        W0s[idx >> 6][idx & 63] = W0[idx];
    }
    __syncthreads();
    int row0 = blockIdx.x * 8;
    int row = row0 + ty;
    float a0 = 0.f, a1 = 0.f;
#pragma unroll
    for (int f = 0; f < FDIM; f++) {
        float xf = X[row * FDIM + f];
        a0 += xf * W0s[f][lane];
        a1 += xf * W0s[f][lane + 32];
    }
    ybuf[ty][lane] = a0;
    ybuf[ty][lane + 32] = a1;
    __syncthreads();
#pragma unroll
    for (int k = 0; k < 2; k++) {
        int v = tid + 256 * k;
        int n = v >> 3, r = v & 7;
        dY0Th[(size_t)n * NNODES + row0 + r] = __float2half_rn(ybuf[r][n]);
    }
}

// ---------------------------------------------------------------------------
// zseg: per-graph block; segment max + softmax sums + bary nums
// ---------------------------------------------------------------------------
__global__ void zseg_kernel(const float *__restrict__ X, const int *__restrict__ I) {
    __shared__ int sb[2];
    __shared__ float red[256];
    int g = blockIdx.x, t = threadIdx.x;
    if (t == 0) {
        int a = 0, b = NNODES;
        while (a < b) { int m = (a + b) >> 1; if (I[m] < g) a = m + 1; else b = m; }
        sb[0] = a;
        b = NNODES;
        while (a < b) { int m = (a + b) >> 1; if (I[m] < g + 1) a = m + 1; else b = m; }
        sb[1] = a;
    }
    __syncthreads();
    int lo = sb[0], hi = sb[1];

    float zmax = 0.f;
    for (int i = lo + t; i < hi; i += 256)
        zmax = fmaxf(zmax, log1pf(fmaxf(X[i * FDIM], 0.f)));
    red[t] = zmax;
    __syncthreads();
    for (int s = 128; s > 0; s >>= 1) {
        if (t < s) red[t] = fmaxf(red[t], red[t + s]);
        __syncthreads();
    }
    zmax = red[0];
    __syncthreads();

    float se = 0.f, s0 = 0.f, s1 = 0.f, s2 = 0.f;
    for (int i = lo + t; i < hi; i += 256) {
        float z = log1pf(fmaxf(X[i * FDIM], 0.f));
        float w = expf(z - zmax);
        se += w;
        s0 += w * X[i * FDIM + 13];
        s1 += w * X[i * FDIM + 14];
        s2 += w * X[i * FDIM + 15];
    }
    float vals[4] = {se, s0, s1, s2};
#pragma unroll
    for (int q = 0; q < 4; q++) {
        red[t] = vals[q];
        __syncthreads();
        for (int s = 128; s > 0; s >>= 1) {
            if (t < s) red[t] += red[t + s];
            __syncthreads();
        }
        vals[q] = red[0];
        __syncthreads();
    }
    if (t == 0) {
        dZsum[g] = vals[0];
        dZnum[g * 3 + 0] = vals[1];
        dZnum[g * 3 + 1] = vals[2];
        dZnum[g * 3 + 2] = vals[3];
    }
}

// ---------------------------------------------------------------------------
// Hybrid GEMM: dZP[y] = fp16(A*8192)[:, y*1024...] @ Bh^T
// A: f32 LDG.128 -> cvt -> STS fp16 (2-stage smem ring, 1-iter register stage)
// B: fp16 cp.async (4-stage ring)
// ---------------------------------------------------------------------------
__global__ void __launch_bounds__(256, 2)
gemm_h(const float *__restrict__ A, const __half *__restrict__ Bh,
       float *__restrict__ C) {
    extern __shared__ char smc[];
    char *As = smc;                       // [2][BM][LDH halfs]
    char *Bs = smc + 2 * STAH;            // [NSTB][64][LDH halfs]

    const int tid = threadIdx.x;
    const int lane = tid & 31, wid = tid >> 5;
    const int wm = wid & 3, wn = wid >> 2;
    const int m0 = blockIdx.x * BM;
    const int kbeg = blockIdx.y * KSPLIT;

    float c[2][4][4] = {};

    // A LDG coords: row = tid>>1 (0..127), half-row seg = tid&1 (16 floats)
    const int ar_ = tid >> 1, as_ = tid & 1;
    const float *gA = A + (size_t)(m0 + ar_) * NNODES + kbeg + as_ * 16;
    __half *sAdst = (__half *)(As) + ar_ * LDH + as_ * 16;
    // B cp.async coords: row = tid>>2 (0..63), chunk = tid&3 (8 halfs)
    const int br_ = tid >> 2, bc_ = tid & 3;
    const __half *gB = Bh + (size_t)br_ * NNODES + kbeg + bc_ * 8;
    const uint32_t sB = (uint32_t)__cvta_generic_to_shared(Bs) + br_ * (LDH * 2) + bc_ * 16;

    // ldmatrix lane offsets (proven pitch-72 pattern)
    const int arow = wm * 32 + (lane & 7) + ((lane >> 3) & 1) * 8;
    const int brow_ = wn * 32 + (lane & 7) + ((lane >> 3) & 1) * 8;
    const int kh = ((lane >> 4) & 1) * 8;

    float4 areg[4];

#define LDG_A(IT)                                                             \
    do {                                                                      \
        const float *p = gA + (size_t)(IT) * BKH;                             \
        areg[0] = ((const float4 *)p)[0];                                     \
        areg[1] = ((const float4 *)p)[1];                                     \
        areg[2] = ((const float4 *)p)[2];                                     \
        areg[3] = ((const float4 *)p)[3];                                     \
    } while (0)

#define STS_A(BUF)                                                            \
    do {                                                                      \
        __half2 h[8];                                                         \
        h[0] = __floats2half2_rn(areg[0].x * ASCALE, areg[0].y * ASCALE);     \
        h[1] = __floats2half2_rn(areg[0].z * ASCALE, areg[0].w * ASCALE);     \
        h[2] = __floats2half2_rn(areg[1].x * ASCALE, areg[1].y * ASCALE);     \
        h[3] = __floats2half2_rn(areg[1].z * ASCALE, areg[1].w * ASCALE);     \
        h[4] = __floats2half2_rn(areg[2].x * ASCALE, areg[2].y * ASCALE);     \
        h[5] = __floats2half2_rn(areg[2].z * ASCALE, areg[2].w * ASCALE);     \
        h[6] = __floats2half2_rn(areg[3].x * ASCALE, areg[3].y * ASCALE);     \
        h[7] = __floats2half2_rn(areg[3].z * ASCALE, areg[3].w * ASCALE);     \
        __half *d_ = sAdst + (BUF) * (STAH / 2);                              \
        ((uint4 *)d_)[0] = *(uint4 *)&h[0];                                   \
        ((uint4 *)d_)[1] = *(uint4 *)&h[4];                                   \
    } while (0)

#define CP_B(IT) cpa16(sB + ((IT) % NSTB) * STBH, gB + (size_t)(IT) * BKH)

#define G_COMPUTE(IT)                                                         \
    do {                                                                      \
        uint32_t abase = (uint32_t)__cvta_generic_to_shared(As) +             \
                         ((IT) & 1) * STAH;                                   \
        uint32_t bbase = (uint32_t)__cvta_generic_to_shared(Bs) +             \
                         ((IT) % NSTB) * STBH;                                \
        _Pragma("unroll") for (int ks = 0; ks < 2; ks++) {                    \
            int kb = ks * 16 + kh;                                            \
            uint32_t a[2][4], b[4][2];                                        \
            _Pragma("unroll") for (int mi = 0; mi < 2; mi++) {                \
                uint32_t addr = abase + (arow + mi * 16) * (LDH * 2) + kb * 2; \
                ldsm4(a[mi][0], a[mi][1], a[mi][2], a[mi][3], addr);          \
            }                                                                 \
            _Pragma("unroll") for (int p = 0; p < 2; p++) {                   \
                uint32_t addr = bbase + (brow_ + p * 16) * (LDH * 2) + kb * 2; \
                uint32_t r0, r1, r2, r3;                                      \
                ldsm4(r0, r1, r2, r3, addr);                                  \
                b[p * 2][0] = r0; b[p * 2 + 1][0] = r1;                       \
                b[p * 2][1] = r2; b[p * 2 + 1][1] = r3;                       \
            }                                                                 \
            _Pragma("unroll") for (int mi = 0; mi < 2; mi++)                  \
                _Pragma("unroll") for (int nj = 0; nj < 4; nj++)              \
                    mma_f16(c[mi][nj], a[mi], b[nj]);                         \
        }                                                                     \
    } while (0)

    // prologue
    LDG_A(0);
    CP_B(0); cpa_commit();
    CP_B(1); cpa_commit();
    CP_B(2); cpa_commit();
    STS_A(0);
    LDG_A(1);
    __syncthreads();

    for (int it = 0; it < NITH; ++it) {
        asm volatile("cp.async.wait_group 2;" ::: "memory");
        __syncthreads();
        G_COMPUTE(it);
        if (it + 3 < NITH) CP_B(it + 3);
        cpa_commit();
        if (it + 1 < NITH) STS_A((it + 1) & 1);
        if (it + 2 < NITH) LDG_A(it + 2);
    }

    float *Cout = C + (size_t)blockIdx.y * NNODES * HDIM;
    int crow = m0 + wm * 32 + (lane >> 2);
    int ccol = wn * 32 + (lane & 3) * 2;
#pragma unroll
    for (int mi = 0; mi < 2; mi++)
#pragma unroll
        for (int nj = 0; nj < 4; nj++) {
            int r = crow + mi * 16, cl = ccol + nj * 8;
            *(float2 *)(Cout + (size_t)r * HDIM + cl) =
                make_float2(c[mi][nj][0], c[mi][nj][1]);
            *(float2 *)(Cout + (size_t)(r + 8) * HDIM + cl) =
                make_float2(c[mi][nj][2], c[mi][nj][3]);
        }
#undef LDG_A
#undef STS_A
#undef CP_B
#undef G_COMPUTE
}

// ---------------------------------------------------------------------------
// mid: h0 = LN(relu(AINV*sum ZP + b0)); store h0 f32; Y1Th fp16
// ---------------------------------------------------------------------------
__global__ void __launch_bounds__(512)
mid_kernel(const float *__restrict__ b0, const float *__restrict__ g0,
           const float *__restrict__ be0, const float *__restrict__ W1) {
    __shared__ float4 W1q[16][64];
    __shared__ __align__(16) float hrow[16][HDIM];
    __shared__ float ybuf[16][68];
    int lane = threadIdx.x, ty = threadIdx.y;
    int tid = ty * 32 + lane;
#pragma unroll
    for (int k = 0; k < 2; k++) {
        int p = tid + 512 * k;
        int t = p >> 6, n = p & 63;
        W1q[t][n] = make_float4(W1[(4 * t + 0) * HDIM + n], W1[(4 * t + 1) * HDIM + n],
                                W1[(4 * t + 2) * HDIM + n], W1[(4 * t + 3) * HDIM + n]);
    }
    __syncthreads();

    int row0 = blockIdx.x * 16;
    int row = row0 + ty;
    float z0 = 0.f, z1 = 0.f;
#pragma unroll
    for (int s = 0; s < NSPLIT; s++) {
        const float *zp = dZP + (size_t)s * NNODES * HDIM + (size_t)row * HDIM;
        z0 += zp[lane];
        z1 += zp[lane + 32];
    }
    z0 = fmaxf(z0 * AINV + b0[lane], 0.f);
    z1 = fmaxf(z1 * AINV + b0[lane + 32], 0.f);
    float s = z0 + z1;
#pragma unroll
    for (int o = 16; o > 0; o >>= 1) s += __shfl_xor_sync(0xffffffffu, s, o);
    float m = s * (1.f / 64.f);
    float d0 = z0 - m, d1 = z1 - m;
    float v = d0 * d0 + d1 * d1;
#pragma unroll
    for (int o = 16; o > 0; o >>= 1) v += __shfl_xor_sync(0xffffffffu, v, o);
    float rs = rsqrtf(v * (1.f / 64.f) + LNEPS);
    float h0a = d0 * rs * g0[lane] + be0[lane];
    float h0b = d1 * rs * g0[lane + 32] + be0[lane + 32];
    dH0[(size_t)row * HDIM + lane] = h0a;
    dH0[(size_t)row * HDIM + lane + 32] = h0b;
    hrow[ty][lane] = h0a;
    hrow[ty][lane + 32] = h0b;
    __syncwarp();
    float a0 = 0.f, a1 = 0.f;
    const float4 *h4 = (const float4 *)&hrow[ty][0];
#pragma unroll
    for (int t = 0; t < 16; t++) {
        float4 h = h4[t];
        float4 wa = W1q[t][lane];
        float4 wb = W1q[t][lane + 32];
        a0 += h.x * wa.x + h.y * wa.y + h.z * wa.z + h.w * wa.w;
        a1 += h.x * wb.x + h.y * wb.y + h.z * wb.z + h.w * wb.w;
    }
    ybuf[ty][lane] = a0;
    ybuf[ty][lane + 32] = a1;
    __syncthreads();
#pragma unroll
    for (int k = 0; k < 2; k++) {
        int p = tid + 512 * k;
        int n = p >> 4, r = p & 15;
        dY1Th[(size_t)n * NNODES + row0 + r] = __float2half_rn(ybuf[r][n]);
    }
}

// ---------------------------------------------------------------------------
// epi2: h = LN(relu(AINV*sum ZP + b1)) + h0; feat/attn matvecs; seg atomics
// ---------------------------------------------------------------------------
__global__ void __launch_bounds__(512)
epi2_kernel(const int *__restrict__ I, const float *__restrict__ b1,
            const float *__restrict__ g1, const float *__restrict__ be1,
            const float *__restrict__ Wf, const float *__restrict__ bf,
            const float *__restrict__ Wa, const float *__restrict__ ba) {
    __shared__ float4 Wfq[16][64];
    __shared__ float4 Waq[16][64];
    __shared__ __align__(16) float hrow[16][HDIM];
    int lane = threadIdx.x, ty = threadIdx.y;
    int tid = ty * 32 + lane;
#pragma unroll
    for (int k = 0; k < 2; k++) {
        int p = tid + 512 * k;
        int t = p >> 6, n = p & 63;
        Wfq[t][n] = make_float4(Wf[(4 * t + 0) * HDIM + n], Wf[(4 * t + 1) * HDIM + n],
                                Wf[(4 * t + 2) * HDIM + n], Wf[(4 * t + 3) * HDIM + n]);
        Waq[t][n] = make_float4(Wa[(4 * t + 0) * HDIM + n], Wa[(4 * t + 1) * HDIM + n],
                                Wa[(4 * t + 2) * HDIM + n], Wa[(4 * t + 3) * HDIM + n]);
    }
    __syncthreads();

    int row = blockIdx.x * 16 + ty;
    float z0 = 0.f, z1 = 0.f;
#pragma unroll
    for (int s = 0; s < NSPLIT; s++) {
        const float *zp = dZP + (size_t)s * NNODES * HDIM + (size_t)row * HDIM;
        z0 += zp[lane];
        z1 += zp[lane + 32];
    }
    z0 = fmaxf(z0 * AINV + b1[lane], 0.f);
    z1 = fmaxf(z1 * AINV + b1[lane + 32], 0.f);
    float s = z0 + z1;
#pragma unroll
    for (int o = 16; o > 0; o >>= 1) s += __shfl_xor_sync(0xffffffffu, s, o);
    float m = s * (1.f / 64.f);
    float d0 = z0 - m, d1 = z1 - m;
    float v = d0 * d0 + d1 * d1;
#pragma unroll
    for (int o = 16; o > 0; o >>= 1) v += __shfl_xor_sync(0xffffffffu, v, o);
    float rs = rsqrtf(v * (1.f / 64.f) + LNEPS);
    float ha = d0 * rs * g1[lane] + be1[lane] + dH0[(size_t)row * HDIM + lane];
    float hb = d1 * rs * g1[lane + 32] + be1[lane + 32] + dH0[(size_t)row * HDIM + lane + 32];
    hrow[ty][lane] = ha;
    hrow[ty][lane + 32] = hb;
    __syncwarp();

    float f0 = bf[lane], f1 = bf[lane + 32];
    float t0 = ba[lane], t1 = ba[lane + 32];
    const float4 *h4 = (const float4 *)&hrow[ty][0];
#pragma unroll
    for (int t = 0; t < 16; t++) {
        float4 h = h4[t];
        float4 fa = Wfq[t][lane];
        float4 fb = Wfq[t][lane + 32];
        float4 aa = Waq[t][lane];
        float4 ab = Waq[t][lane + 32];
        f0 += h.x * fa.x + h.y * fa.y + h.z * fa.z + h.w * fa.w;
        f1 += h.x * fb.x + h.y * fb.y + h.z * fb.z + h.w * fb.w;
        t0 += h.x * aa.x + h.y * aa.y + h.z * aa.z + h.w * aa.w;
        t1 += h.x * ab.x + h.y * ab.y + h.z * ab.z + h.w * ab.w;
    }
    t0 = 1.f / (1.f + expf(-t0));
    t1 = 1.f / (1.f + expf(-t1));
    int g = I[row];
    atomicAdd(&dG[g * HDIM + lane], f0 * t0);
    atomicAdd(&dG[g * HDIM + lane + 32], f1 * t1);
}

// ---------------------------------------------------------------------------
// final: out[g] = [Gacc[g] | bary[g]] @ Wout + bout
// ---------------------------------------------------------------------------
__global__ void final_kernel(const float *__restrict__ Wout,
                             const float *__restrict__ bout, float *__restrict__ out) {
    int g = blockIdx.x * 64 + threadIdx.x;
    if (g >= GSEG) return;
    float a0 = bout[0], a1 = bout[1], a2 = bout[2];
#pragma unroll
    for (int j = 0; j < HDIM; j++) {
        float v = dG[g * HDIM + j];
        a0 += v * Wout[j * 3 + 0];
        a1 += v * Wout[j * 3 + 1];
        a2 += v * Wout[j * 3 + 2];
    }
    float zs = dZsum[g];
    float inv = zs > 0.f ? 1.f / zs : 0.f;
#pragma unroll
    for (int d = 0; d < 3; d++) {
        float b = dZnum[g * 3 + d] * inv;
        a0 += b * Wout[(HDIM + d) * 3 + 0];
        a1 += b * Wout[(HDIM + d) * 3 + 1];
        a2 += b * Wout[(HDIM + d) * 3 + 2];
    }
    out[g * 3 + 0] = a0;
    out[g * 3 + 1] = a1;
    out[g * 3 + 2] = a2;
}

// ---------------------------------------------------------------------------
// launch
// ---------------------------------------------------------------------------
extern "C" void kernel_launch(void *const *d_in, const int *in_sizes, int n_in,
                              void *d_out, int out_size) {
    const float *X = (const float *)d_in[0];
    const float *A = (const float *)d_in[1];
    const int *I = (const int *)d_in[2];
    const float *W0 = (const float *)d_in[3];
    const float *b0 = (const float *)d_in[4];
    const float *g0 = (const float *)d_in[5];
    const float *be0 = (const float *)d_in[6];
    const float *W1 = (const float *)d_in[7];
    const float *b1 = (const float *)d_in[8];
    const float *g1 = (const float *)d_in[9];
    const float *be1 = (const float *)d_in[10];
    const float *Wf = (const float *)d_in[11];
    const float *bf = (const float *)d_in[12];
    const float *Wa = (const float *)d_in[13];
    const float *ba = (const float *)d_in[14];
    const float *Wout = (const float *)d_in[15];
    const float *bout = (const float *)d_in[16];
    float *out = (float *)d_out;

    float *zp;
    __half *y0th, *y1th;
    cudaGetSymbolAddress((void **)&zp, dZP);
    cudaGetSymbolAddress((void **)&y0th, dY0Th);
    cudaGetSymbolAddress((void **)&y1th, dY1Th);

    cudaFuncSetAttribute(gemm_h, cudaFuncAttributeMaxDynamicSharedMemorySize, SMEMG);

    initg_kernel<<<64, 256>>>();
    y0t_kernel<<<NNODES / 8, dim3(32, 8)>>>(X, W0);
    zseg_kernel<<<GSEG, 256>>>(X, I);
    gemm_h<<<dim3(NNODES / BM, NSPLIT), 256, SMEMG>>>(A, y0th, zp);
    mid_kernel<<<NNODES / 16, dim3(32, 16)>>>(b0, g0, be0, W1);
    gemm_h<<<dim3(NNODES / BM, NSPLIT), 256, SMEMG>>>(A, y1th, zp);
    epi2_kernel<<<NNODES / 16, dim3(32, 16)>>>(I, b1, g1, be1, Wf, bf, Wa, ba);
    final_kernel<<<(GSEG + 63) / 64, 64>>>(Wout, bout, out);
}

// round 14
// speedup vs baseline: 1.0349x; 1.0349x over previous
#include <cuda_runtime.h>
#include <cuda_fp16.h>
#include <cstdint>
#include <math.h>

// ---------------------------------------------------------------------------
// Problem constants
// ---------------------------------------------------------------------------
#define NNODES 8192
#define FDIM   16
#define HDIM   64
#define GSEG   256
#define LNEPS  1e-3f
#define ASCALE 8192.0f
#define AINV   (1.0f / 8192.0f)

#define NSPLIT 4
#define KSPLIT (NNODES / NSPLIT)   // 2048
#define BM 128

// GEMM1 (hybrid): A f32 LDG->cvt->{STS fp16, STG Ah}, B fp16 cp.async
#define BKH 32
#define NITH (KSPLIT / BKH)        // 64
#define LDH 72                     // half pitch (144 B)
#define STAH (BM * LDH * 2)        // 18432 B
#define STBH (64 * LDH * 2)        // 9216 B
#define NSTB 4
#define SMEM1 (2 * STAH + NSTB * STBH)  // 73728 B

// GEMM2 (fp16, BK=32, 3 CTAs/SM)
#define BK2 32
#define NIT2 (KSPLIT / BK2)        // 64
#define LD2 40                     // half pitch (80 B) -- conflict-free mod 128
#define ST2A (BM * LD2 * 2)        // 10240 B
#define ST2B (64 * LD2 * 2)        // 5120 B
#define NST2 4
#define SMEM2 (NST2 * (ST2A + ST2B))   // 61440 B

// ---------------------------------------------------------------------------
// Device scratch
// ---------------------------------------------------------------------------
__device__ __half dAh[(size_t)NNODES * NNODES];   // A * 8192 fp16 (128 MB)
__device__ __half dY0Th[HDIM * NNODES];           // (X@W0)^T fp16
__device__ __half dY1Th[HDIM * NNODES];           // (h0@W1)^T fp16
__device__ float dZP[NSPLIT * NNODES * HDIM];     // split-K partials
__device__ float dH0[NNODES * HDIM];
__device__ float dG[GSEG * HDIM];
__device__ float dZsum[GSEG];
__device__ float dZnum[GSEG * 3];

// ---------------------------------------------------------------------------
// PTX helpers
// ---------------------------------------------------------------------------
__device__ __forceinline__ void cpa16(uint32_t dst, const void *src) {
    asm volatile("cp.async.cg.shared.global [%0], [%1], 16;" ::"r"(dst), "l"(src));
}
__device__ __forceinline__ void cpa_commit() {
    asm volatile("cp.async.commit_group;");
}
__device__ __forceinline__ void ldsm4(uint32_t &r0, uint32_t &r1, uint32_t &r2,
                                      uint32_t &r3, uint32_t addr) {
    asm volatile("ldmatrix.sync.aligned.m8n8.x4.shared.b16 {%0,%1,%2,%3}, [%4];"
                 : "=r"(r0), "=r"(r1), "=r"(r2), "=r"(r3) : "r"(addr));
}
__device__ __forceinline__ void mma_f16(float c[4], const uint32_t a[4],
                                        const uint32_t b[2]) {
    asm volatile(
        "mma.sync.aligned.m16n8k16.row.col.f32.f16.f16.f32 "
        "{%0,%1,%2,%3}, {%4,%5,%6,%7}, {%8,%9}, {%0,%1,%2,%3};"
        : "+f"(c[0]), "+f"(c[1]), "+f"(c[2]), "+f"(c[3])
        : "r"(a[0]), "r"(a[1]), "r"(a[2]), "r"(a[3]), "r"(b[0]), "r"(b[1]));
}

// ---------------------------------------------------------------------------
// initg: zero dG (launch spacer so gemm1 is 4th for ncu)
// ---------------------------------------------------------------------------
__global__ void initg_kernel() {
    int i = blockIdx.x * 256 + threadIdx.x;
    if (i < GSEG * HDIM) dG[i] = 0.f;
}

// ---------------------------------------------------------------------------
// y0t: Y0Th[n][i] = fp16(sum_f X[i][f]*W0[f][n])
// ---------------------------------------------------------------------------
__global__ void y0t_kernel(const float *__restrict__ X, const float *__restrict__ W0) {
    __shared__ float W0s[FDIM][HDIM];
    __shared__ float ybuf[8][68];
    int lane = threadIdx.x, ty = threadIdx.y;
    int tid = ty * 32 + lane;
#pragma unroll
    for (int j = 0; j < 4; j++) {
        int idx = tid + 256 * j;
        W0s[idx >> 6][idx & 63] = W0[idx];
    }
    __syncthreads();
    int row0 = blockIdx.x * 8;
    int row = row0 + ty;
    float a0 = 0.f, a1 = 0.f;
#pragma unroll
    for (int f = 0; f < FDIM; f++) {
        float xf = X[row * FDIM + f];
        a0 += xf * W0s[f][lane];
        a1 += xf * W0s[f][lane + 32];
    }
    ybuf[ty][lane] = a0;
    ybuf[ty][lane + 32] = a1;
    __syncthreads();
#pragma unroll
    for (int k = 0; k < 2; k++) {
        int v = tid + 256 * k;
        int n = v >> 3, r = v & 7;
        dY0Th[(size_t)n * NNODES + row0 + r] = __float2half_rn(ybuf[r][n]);
    }
}

// ---------------------------------------------------------------------------
// zseg: per-graph block; segment max + softmax sums + bary nums
// ---------------------------------------------------------------------------
__global__ void zseg_kernel(const float *__restrict__ X, const int *__restrict__ I) {
    __shared__ int sb[2];
    __shared__ float red[256];
    int g = blockIdx.x, t = threadIdx.x;
    if (t == 0) {
        int a = 0, b = NNODES;
        while (a < b) { int m = (a + b) >> 1; if (I[m] < g) a = m + 1; else b = m; }
        sb[0] = a;
        b = NNODES;
        while (a < b) { int m = (a + b) >> 1; if (I[m] < g + 1) a = m + 1; else b = m; }
        sb[1] = a;
    }
    __syncthreads();
    int lo = sb[0], hi = sb[1];

    float zmax = 0.f;
    for (int i = lo + t; i < hi; i += 256)
        zmax = fmaxf(zmax, log1pf(fmaxf(X[i * FDIM], 0.f)));
    red[t] = zmax;
    __syncthreads();
    for (int s = 128; s > 0; s >>= 1) {
        if (t < s) red[t] = fmaxf(red[t], red[t + s]);
        __syncthreads();
    }
    zmax = red[0];
    __syncthreads();

    float se = 0.f, s0 = 0.f, s1 = 0.f, s2 = 0.f;
    for (int i = lo + t; i < hi; i += 256) {
        float z = log1pf(fmaxf(X[i * FDIM], 0.f));
        float w = expf(z - zmax);
        se += w;
        s0 += w * X[i * FDIM + 13];
        s1 += w * X[i * FDIM + 14];
        s2 += w * X[i * FDIM + 15];
    }
    float vals[4] = {se, s0, s1, s2};
#pragma unroll
    for (int q = 0; q < 4; q++) {
        red[t] = vals[q];
        __syncthreads();
        for (int s = 128; s > 0; s >>= 1) {
            if (t < s) red[t] += red[t + s];
            __syncthreads();
        }
        vals[q] = red[0];
        __syncthreads();
    }
    if (t == 0) {
        dZsum[g] = vals[0];
        dZnum[g * 3 + 0] = vals[1];
        dZnum[g * 3 + 1] = vals[2];
        dZnum[g * 3 + 2] = vals[3];
    }
}

// ---------------------------------------------------------------------------
// GEMM1 hybrid: dZP[y] = fp16(A*8192)[:, y*2048...] @ Bh^T ; also writes dAh
// A: f32 LDG.128 -> cvt -> STS fp16 + STG fp16 (registers, no re-read)
// B: fp16 cp.async (4-stage ring)
// ---------------------------------------------------------------------------
__global__ void __launch_bounds__(256, 2)
gemm_h(const float *__restrict__ A, const __half *__restrict__ Bh,
       float *__restrict__ C, __half *__restrict__ Ah) {
    extern __shared__ char smc[];
    char *As = smc;                       // [2][BM][LDH halfs]
    char *Bs = smc + 2 * STAH;            // [NSTB][64][LDH halfs]

    const int tid = threadIdx.x;
    const int lane = tid & 31, wid = tid >> 5;
    const int wm = wid & 3, wn = wid >> 2;
    const int m0 = blockIdx.x * BM;
    const int kbeg = blockIdx.y * KSPLIT;

    float c[2][4][4] = {};

    const int ar_ = tid >> 1, as_ = tid & 1;
    const float *gA = A + (size_t)(m0 + ar_) * NNODES + kbeg + as_ * 16;
    __half *sAdst = (__half *)(As) + ar_ * LDH + as_ * 16;
    __half *gAh = Ah + (size_t)(m0 + ar_) * NNODES + kbeg + as_ * 16;
    const int br_ = tid >> 2, bc_ = tid & 3;
    const __half *gB = Bh + (size_t)br_ * NNODES + kbeg + bc_ * 8;
    const uint32_t sB = (uint32_t)__cvta_generic_to_shared(Bs) + br_ * (LDH * 2) + bc_ * 16;

    const int arow = wm * 32 + (lane & 7) + ((lane >> 3) & 1) * 8;
    const int brow_ = wn * 32 + (lane & 7) + ((lane >> 3) & 1) * 8;
    const int kh = ((lane >> 4) & 1) * 8;

    float4 areg[4];

#define LDG_A(IT)                                                             \
    do {                                                                      \
        const float *p = gA + (size_t)(IT) * BKH;                             \
        areg[0] = ((const float4 *)p)[0];                                     \
        areg[1] = ((const float4 *)p)[1];                                     \
        areg[2] = ((const float4 *)p)[2];                                     \
        areg[3] = ((const float4 *)p)[3];                                     \
    } while (0)

#define STS_A(IT)                                                             \
    do {                                                                      \
        __half2 h[8];                                                         \
        h[0] = __floats2half2_rn(areg[0].x * ASCALE, areg[0].y * ASCALE);     \
        h[1] = __floats2half2_rn(areg[0].z * ASCALE, areg[0].w * ASCALE);     \
        h[2] = __floats2half2_rn(areg[1].x * ASCALE, areg[1].y * ASCALE);     \
        h[3] = __floats2half2_rn(areg[1].z * ASCALE, areg[1].w * ASCALE);     \
        h[4] = __floats2half2_rn(areg[2].x * ASCALE, areg[2].y * ASCALE);     \
        h[5] = __floats2half2_rn(areg[2].z * ASCALE, areg[2].w * ASCALE);     \
        h[6] = __floats2half2_rn(areg[3].x * ASCALE, areg[3].y * ASCALE);     \
        h[7] = __floats2half2_rn(areg[3].z * ASCALE, areg[3].w * ASCALE);     \
        __half *d_ = sAdst + ((IT) & 1) * (STAH / 2);                         \
        ((uint4 *)d_)[0] = *(uint4 *)&h[0];                                   \
        ((uint4 *)d_)[1] = *(uint4 *)&h[4];                                   \
        __half *g_ = gAh + (size_t)(IT) * BKH;                                \
        ((uint4 *)g_)[0] = *(uint4 *)&h[0];                                   \
        ((uint4 *)g_)[1] = *(uint4 *)&h[4];                                   \
    } while (0)

#define CP_B(IT) cpa16(sB + ((IT) % NSTB) * STBH, gB + (size_t)(IT) * BKH)

#define G_COMPUTE(IT)                                                         \
    do {                                                                      \
        uint32_t abase = (uint32_t)__cvta_generic_to_shared(As) +             \
                         ((IT) & 1) * STAH;                                   \
        uint32_t bbase = (uint32_t)__cvta_generic_to_shared(Bs) +             \
                         ((IT) % NSTB) * STBH;                                \
        _Pragma("unroll") for (int ks = 0; ks < 2; ks++) {                    \
            int kb = ks * 16 + kh;                                            \
            uint32_t a[2][4], b[4][2];                                        \
            _Pragma("unroll") for (int mi = 0; mi < 2; mi++) {                \
                uint32_t addr = abase + (arow + mi * 16) * (LDH * 2) + kb * 2; \
                ldsm4(a[mi][0], a[mi][1], a[mi][2], a[mi][3], addr);          \
            }                                                                 \
            _Pragma("unroll") for (int p = 0; p < 2; p++) {                   \
                uint32_t addr = bbase + (brow_ + p * 16) * (LDH * 2) + kb * 2; \
                uint32_t r0, r1, r2, r3;                                      \
                ldsm4(r0, r1, r2, r3, addr);                                  \
                b[p * 2][0] = r0; b[p * 2 + 1][0] = r1;                       \
                b[p * 2][1] = r2; b[p * 2 + 1][1] = r3;                       \
            }                                                                 \
            _Pragma("unroll") for (int mi = 0; mi < 2; mi++)                  \
                _Pragma("unroll") for (int nj = 0; nj < 4; nj++)              \
                    mma_f16(c[mi][nj], a[mi], b[nj]);                         \
        }                                                                     \
    } while (0)

    // prologue
    LDG_A(0);
    CP_B(0); cpa_commit();
    CP_B(1); cpa_commit();
    CP_B(2); cpa_commit();
    STS_A(0);
    LDG_A(1);
    __syncthreads();

    for (int it = 0; it < NITH; ++it) {
        asm volatile("cp.async.wait_group 2;" ::: "memory");
        __syncthreads();
        G_COMPUTE(it);
        if (it + 3 < NITH) CP_B(it + 3);
        cpa_commit();
        if (it + 1 < NITH) STS_A(it + 1);
        if (it + 2 < NITH) LDG_A(it + 2);
    }

    float *Cout = C + (size_t)blockIdx.y * NNODES * HDIM;
    int crow = m0 + wm * 32 + (lane >> 2);
    int ccol = wn * 32 + (lane & 3) * 2;
#pragma unroll
    for (int mi = 0; mi < 2; mi++)
#pragma unroll
        for (int nj = 0; nj < 4; nj++) {
            int r = crow + mi * 16, cl = ccol + nj * 8;
            *(float2 *)(Cout + (size_t)r * HDIM + cl) =
                make_float2(c[mi][nj][0], c[mi][nj][1]);
            *(float2 *)(Cout + (size_t)(r + 8) * HDIM + cl) =
                make_float2(c[mi][nj][2], c[mi][nj][3]);
        }
#undef LDG_A
#undef STS_A
#undef CP_B
#undef G_COMPUTE
}

// ---------------------------------------------------------------------------
// GEMM2 (fp16, BK=32, 3 CTAs/SM, 24 warps): dZP[y] = Ah[:, y*2048...] @ Bh^T
// ---------------------------------------------------------------------------
__global__ void __launch_bounds__(256, 3)
gemm2_f16(const __half *__restrict__ Ah, const __half *__restrict__ Bh,
          float *__restrict__ C) {
    extern __shared__ char smc[];
    char *As = smc;                       // [NST2][BM][LD2 halfs]
    char *Bs = smc + NST2 * ST2A;         // [NST2][64][LD2 halfs]

    const int tid = threadIdx.x;
    const int lane = tid & 31, wid = tid >> 5;
    const int wm = wid & 3, wn = wid >> 2;
    const int m0 = blockIdx.x * BM;
    const int kbeg = blockIdx.y * KSPLIT;

    float c[2][4][4] = {};

    // cp.async coords: row = tid>>2 (0..63, +64 via j), chunk = tid&3 (16 B)
    const int r_ = tid >> 2, c_ = tid & 3;
    const __half *gA = Ah + (size_t)(m0 + r_) * NNODES + kbeg + c_ * 8;
    const __half *gB = Bh + (size_t)r_ * NNODES + kbeg + c_ * 8;
    const uint32_t sA = (uint32_t)__cvta_generic_to_shared(As) + r_ * (LD2 * 2) + c_ * 16;
    const uint32_t sB = (uint32_t)__cvta_generic_to_shared(Bs) + r_ * (LD2 * 2) + c_ * 16;

    const int arow = wm * 32 + (lane & 7) + ((lane >> 3) & 1) * 8;
    const int brow_ = wn * 32 + (lane & 7) + ((lane >> 3) & 1) * 8;
    const int kh = ((lane >> 4) & 1) * 8;

#define G2_ISSUE(IT)                                                          \
    do {                                                                      \
        int buf = (IT) % NST2;                                                \
        size_t koff = (size_t)(IT) * BK2;                                     \
        uint32_t da = sA + buf * ST2A;                                        \
        uint32_t db = sB + buf * ST2B;                                        \
        cpa16(da, gA + koff);                                                 \
        cpa16(da + 64 * (LD2 * 2), gA + koff + (size_t)64 * NNODES);          \
        cpa16(db, gB + koff);                                                 \
    } while (0)

#define G2_COMPUTE(BUF)                                                       \
    do {                                                                      \
        uint32_t abase = (uint32_t)__cvta_generic_to_shared(As) + (BUF) * ST2A; \
        uint32_t bbase = (uint32_t)__cvta_generic_to_shared(Bs) + (BUF) * ST2B; \
        _Pragma("unroll") for (int ks = 0; ks < 2; ks++) {                    \
            int kb = ks * 16 + kh;                                            \
            uint32_t a[2][4], b[4][2];                                        \
            _Pragma("unroll") for (int mi = 0; mi < 2; mi++) {                \
                uint32_t addr = abase + (arow + mi * 16) * (LD2 * 2) + kb * 2; \
                ldsm4(a[mi][0], a[mi][1], a[mi][2], a[mi][3], addr);          \
            }                                                                 \
            _Pragma("unroll") for (int p = 0; p < 2; p++) {                   \
                uint32_t addr = bbase + (brow_ + p * 16) * (LD2 * 2) + kb * 2; \
                uint32_t r0, r1, r2, r3;                                      \
                ldsm4(r0, r1, r2, r3, addr);                                  \
                b[p * 2][0] = r0; b[p * 2 + 1][0] = r1;                       \
                b[p * 2][1] = r2; b[p * 2 + 1][1] = r3;                       \
            }                                                                 \
            _Pragma("unroll") for (int mi = 0; mi < 2; mi++)                  \
                _Pragma("unroll") for (int nj = 0; nj < 4; nj++)              \
                    mma_f16(c[mi][nj], a[mi], b[nj]);                         \
        }                                                                     \
    } while (0)

#pragma unroll
    for (int s = 0; s < NST2 - 1; s++) {
        G2_ISSUE(s);
        cpa_commit();
    }

    for (int it = 0; it < NIT2; ++it) {
        asm volatile("cp.async.wait_group 2;" ::: "memory");
        __syncthreads();
        if (it + NST2 - 1 < NIT2) G2_ISSUE(it + NST2 - 1);
        cpa_commit();
        G2_COMPUTE(it % NST2);
    }

    float *Cout = C + (size_t)blockIdx.y * NNODES * HDIM;
    int crow = m0 + wm * 32 + (lane >> 2);
    int ccol = wn * 32 + (lane & 3) * 2;
#pragma unroll
    for (int mi = 0; mi < 2; mi++)
#pragma unroll
        for (int nj = 0; nj < 4; nj++) {
            int r = crow + mi * 16, cl = ccol + nj * 8;
            *(float2 *)(Cout + (size_t)r * HDIM + cl) =
                make_float2(c[mi][nj][0], c[mi][nj][1]);
            *(float2 *)(Cout + (size_t)(r + 8) * HDIM + cl) =
                make_float2(c[mi][nj][2], c[mi][nj][3]);
        }
#undef G2_ISSUE
#undef G2_COMPUTE
}

// ---------------------------------------------------------------------------
// mid: h0 = LN(relu(AINV*sum ZP + b0)); store h0 f32; Y1Th fp16
// ---------------------------------------------------------------------------
__global__ void __launch_bounds__(512)
mid_kernel(const float *__restrict__ b0, const float *__restrict__ g0,
           const float *__restrict__ be0, const float *__restrict__ W1) {
    __shared__ float4 W1q[16][64];
    __shared__ __align__(16) float hrow[16][HDIM];
    __shared__ float ybuf[16][68];
    int lane = threadIdx.x, ty = threadIdx.y;
    int tid = ty * 32 + lane;
#pragma unroll
    for (int k = 0; k < 2; k++) {
        int p = tid + 512 * k;
        int t = p >> 6, n = p & 63;
        W1q[t][n] = make_float4(W1[(4 * t + 0) * HDIM + n], W1[(4 * t + 1) * HDIM + n],
                                W1[(4 * t + 2) * HDIM + n], W1[(4 * t + 3) * HDIM + n]);
    }
    __syncthreads();

    int row0 = blockIdx.x * 16;
    int row = row0 + ty;
    float z0 = 0.f, z1 = 0.f;
#pragma unroll
    for (int s = 0; s < NSPLIT; s++) {
        const float *zp = dZP + (size_t)s * NNODES * HDIM + (size_t)row * HDIM;
        z0 += zp[lane];
        z1 += zp[lane + 32];
    }
    z0 = fmaxf(z0 * AINV + b0[lane], 0.f);
    z1 = fmaxf(z1 * AINV + b0[lane + 32], 0.f);
    float s = z0 + z1;
#pragma unroll
    for (int o = 16; o > 0; o >>= 1) s += __shfl_xor_sync(0xffffffffu, s, o);
    float m = s * (1.f / 64.f);
    float d0 = z0 - m, d1 = z1 - m;
    float v = d0 * d0 + d1 * d1;
#pragma unroll
    for (int o = 16; o > 0; o >>= 1) v += __shfl_xor_sync(0xffffffffu, v, o);
    float rs = rsqrtf(v * (1.f / 64.f) + LNEPS);
    float h0a = d0 * rs * g0[lane] + be0[lane];
    float h0b = d1 * rs * g0[lane + 32] + be0[lane + 32];
    dH0[(size_t)row * HDIM + lane] = h0a;
    dH0[(size_t)row * HDIM + lane + 32] = h0b;
    hrow[ty][lane] = h0a;
    hrow[ty][lane + 32] = h0b;
    __syncwarp();
    float a0 = 0.f, a1 = 0.f;
    const float4 *h4 = (const float4 *)&hrow[ty][0];
#pragma unroll
    for (int t = 0; t < 16; t++) {
        float4 h = h4[t];
        float4 wa = W1q[t][lane];
        float4 wb = W1q[t][lane + 32];
        a0 += h.x * wa.x + h.y * wa.y + h.z * wa.z + h.w * wa.w;
        a1 += h.x * wb.x + h.y * wb.y + h.z * wb.z + h.w * wb.w;
    }
    ybuf[ty][lane] = a0;
    ybuf[ty][lane + 32] = a1;
    __syncthreads();
#pragma unroll
    for (int k = 0; k < 2; k++) {
        int p = tid + 512 * k;
        int n = p >> 4, r = p & 15;
        dY1Th[(size_t)n * NNODES + row0 + r] = __float2half_rn(ybuf[r][n]);
    }
}

// ---------------------------------------------------------------------------
// epi2: h = LN(relu(AINV*sum ZP + b1)) + h0; feat/attn matvecs; seg atomics
// ---------------------------------------------------------------------------
__global__ void __launch_bounds__(512)
epi2_kernel(const int *__restrict__ I, const float *__restrict__ b1,
            const float *__restrict__ g1, const float *__restrict__ be1,
            const float *__restrict__ Wf, const float *__restrict__ bf,
            const float *__restrict__ Wa, const float *__restrict__ ba) {
    __shared__ float4 Wfq[16][64];
    __shared__ float4 Waq[16][64];
    __shared__ __align__(16) float hrow[16][HDIM];
    int lane = threadIdx.x, ty = threadIdx.y;
    int tid = ty * 32 + lane;
#pragma unroll
    for (int k = 0; k < 2; k++) {
        int p = tid + 512 * k;
        int t = p >> 6, n = p & 63;
        Wfq[t][n] = make_float4(Wf[(4 * t + 0) * HDIM + n], Wf[(4 * t + 1) * HDIM + n],
                                Wf[(4 * t + 2) * HDIM + n], Wf[(4 * t + 3) * HDIM + n]);
        Waq[t][n] = make_float4(Wa[(4 * t + 0) * HDIM + n], Wa[(4 * t + 1) * HDIM + n],
                                Wa[(4 * t + 2) * HDIM + n], Wa[(4 * t + 3) * HDIM + n]);
    }
    __syncthreads();

    int row = blockIdx.x * 16 + ty;
    float z0 = 0.f, z1 = 0.f;
#pragma unroll
    for (int s = 0; s < NSPLIT; s++) {
        const float *zp = dZP + (size_t)s * NNODES * HDIM + (size_t)row * HDIM;
        z0 += zp[lane];
        z1 += zp[lane + 32];
    }
    z0 = fmaxf(z0 * AINV + b1[lane], 0.f);
    z1 = fmaxf(z1 * AINV + b1[lane + 32], 0.f);
    float s = z0 + z1;
#pragma unroll
    for (int o = 16; o > 0; o >>= 1) s += __shfl_xor_sync(0xffffffffu, s, o);
    float m = s * (1.f / 64.f);
    float d0 = z0 - m, d1 = z1 - m;
    float v = d0 * d0 + d1 * d1;
#pragma unroll
    for (int o = 16; o > 0; o >>= 1) v += __shfl_xor_sync(0xffffffffu, v, o);
    float rs = rsqrtf(v * (1.f / 64.f) + LNEPS);
    float ha = d0 * rs * g1[lane] + be1[lane] + dH0[(size_t)row * HDIM + lane];
    float hb = d1 * rs * g1[lane + 32] + be1[lane + 32] + dH0[(size_t)row * HDIM + lane + 32];
    hrow[ty][lane] = ha;
    hrow[ty][lane + 32] = hb;
    __syncwarp();

    float f0 = bf[lane], f1 = bf[lane + 32];
    float t0 = ba[lane], t1 = ba[lane + 32];
    const float4 *h4 = (const float4 *)&hrow[ty][0];
#pragma unroll
    for (int t = 0; t < 16; t++) {
        float4 h = h4[t];
        float4 fa = Wfq[t][lane];
        float4 fb = Wfq[t][lane + 32];
        float4 aa = Waq[t][lane];
        float4 ab = Waq[t][lane + 32];
        f0 += h.x * fa.x + h.y * fa.y + h.z * fa.z + h.w * fa.w;
        f1 += h.x * fb.x + h.y * fb.y + h.z * fb.z + h.w * fb.w;
        t0 += h.x * aa.x + h.y * aa.y + h.z * aa.z + h.w * aa.w;
        t1 += h.x * ab.x + h.y * ab.y + h.z * ab.z + h.w * ab.w;
    }
    t0 = 1.f / (1.f + expf(-t0));
    t1 = 1.f / (1.f + expf(-t1));
    int g = I[row];
    atomicAdd(&dG[g * HDIM + lane], f0 * t0);
    atomicAdd(&dG[g * HDIM + lane + 32], f1 * t1);
}

// ---------------------------------------------------------------------------
// final: out[g] = [Gacc[g] | bary[g]] @ Wout + bout
// ---------------------------------------------------------------------------
__global__ void final_kernel(const float *__restrict__ Wout,
                             const float *__restrict__ bout, float *__restrict__ out) {
    int g = blockIdx.x * 64 + threadIdx.x;
    if (g >= GSEG) return;
    float a0 = bout[0], a1 = bout[1], a2 = bout[2];
#pragma unroll
    for (int j = 0; j < HDIM; j++) {
        float v = dG[g * HDIM + j];
        a0 += v * Wout[j * 3 + 0];
        a1 += v * Wout[j * 3 + 1];
        a2 += v * Wout[j * 3 + 2];
    }
    float zs = dZsum[g];
    float inv = zs > 0.f ? 1.f / zs : 0.f;
#pragma unroll
    for (int d = 0; d < 3; d++) {
        float b = dZnum[g * 3 + d] * inv;
        a0 += b * Wout[(HDIM + d) * 3 + 0];
        a1 += b * Wout[(HDIM + d) * 3 + 1];
        a2 += b * Wout[(HDIM + d) * 3 + 2];
    }
    out[g * 3 + 0] = a0;
    out[g * 3 + 1] = a1;
    out[g * 3 + 2] = a2;
}

// ---------------------------------------------------------------------------
// launch
// ---------------------------------------------------------------------------
extern "C" void kernel_launch(void *const *d_in, const int *in_sizes, int n_in,
                              void *d_out, int out_size) {
    const float *X = (const float *)d_in[0];
    const float *A = (const float *)d_in[1];
    const int *I = (const int *)d_in[2];
    const float *W0 = (const float *)d_in[3];
    const float *b0 = (const float *)d_in[4];
    const float *g0 = (const float *)d_in[5];
    const float *be0 = (const float *)d_in[6];
    const float *W1 = (const float *)d_in[7];
    const float *b1 = (const float *)d_in[8];
    const float *g1 = (const float *)d_in[9];
    const float *be1 = (const float *)d_in[10];
    const float *Wf = (const float *)d_in[11];
    const float *bf = (const float *)d_in[12];
    const float *Wa = (const float *)d_in[13];
    const float *ba = (const float *)d_in[14];
    const float *Wout = (const float *)d_in[15];
    const float *bout = (const float *)d_in[16];
    float *out = (float *)d_out;

    float *zp;
    __half *ah, *y0th, *y1th;
    cudaGetSymbolAddress((void **)&zp, dZP);
    cudaGetSymbolAddress((void **)&ah, dAh);
    cudaGetSymbolAddress((void **)&y0th, dY0Th);
    cudaGetSymbolAddress((void **)&y1th, dY1Th);

    cudaFuncSetAttribute(gemm_h, cudaFuncAttributeMaxDynamicSharedMemorySize, SMEM1);
    cudaFuncSetAttribute(gemm2_f16, cudaFuncAttributeMaxDynamicSharedMemorySize, SMEM2);

    initg_kernel<<<64, 256>>>();
    y0t_kernel<<<NNODES / 8, dim3(32, 8)>>>(X, W0);
    zseg_kernel<<<GSEG, 256>>>(X, I);
    gemm_h<<<dim3(NNODES / BM, NSPLIT), 256, SMEM1>>>(A, y0th, zp, ah);
    mid_kernel<<<NNODES / 16, dim3(32, 16)>>>(b0, g0, be0, W1);
    gemm2_f16<<<dim3(NNODES / BM, NSPLIT), 256, SMEM2>>>(ah, y1th, zp);
    epi2_kernel<<<NNODES / 16, dim3(32, 16)>>>(I, b1, g1, be1, Wf, bf, Wa, ba);
    final_kernel<<<(GSEG + 63) / 64, 64>>>(Wout, bout, out);
}

// round 15
// speedup vs baseline: 1.0572x; 1.0215x over previous
#include <cuda_runtime.h>
#include <cuda_fp16.h>
#include <cstdint>
#include <math.h>

// ---------------------------------------------------------------------------
// Problem constants
// ---------------------------------------------------------------------------
#define NNODES 8192
#define FDIM   16
#define HDIM   64
#define GSEG   256
#define LNEPS  1e-3f
#define ASCALE 8192.0f
#define AINV   (1.0f / 8192.0f)

#define NSPLIT 2
#define KSPLIT (NNODES / NSPLIT)   // 4096
#define BM 128

// GEMM (fp16 m16n8k16, 512 threads, 16 warps: 4m x 2n x 2kg)
#define BK2 64
#define NIT2 (KSPLIT / BK2)        // 64
#define LDH 72                     // half pitch (144 B), proven conflict-free
#define ST2A (BM * LDH * 2)        // 18432 B
#define ST2B (64 * LDH * 2)        // 9216 B
#define NST2 4
#define SMEM2 (NST2 * (ST2A + ST2B))   // 110592 B

// ---------------------------------------------------------------------------
// Device scratch
// ---------------------------------------------------------------------------
__device__ __half dAh[(size_t)NNODES * NNODES];   // A * 8192 fp16 (128 MB)
__device__ __half dY0Th[HDIM * NNODES];           // (X@W0)^T fp16
__device__ __half dY1Th[HDIM * NNODES];           // (h0@W1)^T fp16
__device__ float dZP[NSPLIT * NNODES * HDIM];     // split-K partials
__device__ float dH0[NNODES * HDIM];
__device__ float dG[GSEG * HDIM];
__device__ float dZsum[GSEG];
__device__ float dZnum[GSEG * 3];

// ---------------------------------------------------------------------------
// PTX helpers
// ---------------------------------------------------------------------------
__device__ __forceinline__ void cpa16(uint32_t dst, const void *src) {
    asm volatile("cp.async.cg.shared.global [%0], [%1], 16;" ::"r"(dst), "l"(src));
}
__device__ __forceinline__ void cpa_commit() {
    asm volatile("cp.async.commit_group;");
}
__device__ __forceinline__ void ldsm4(uint32_t &r0, uint32_t &r1, uint32_t &r2,
                                      uint32_t &r3, uint32_t addr) {
    asm volatile("ldmatrix.sync.aligned.m8n8.x4.shared.b16 {%0,%1,%2,%3}, [%4];"
                 : "=r"(r0), "=r"(r1), "=r"(r2), "=r"(r3) : "r"(addr));
}
__device__ __forceinline__ void mma_f16(float c[4], const uint32_t a[4],
                                        const uint32_t b[2]) {
    asm volatile(
        "mma.sync.aligned.m16n8k16.row.col.f32.f16.f16.f32 "
        "{%0,%1,%2,%3}, {%4,%5,%6,%7}, {%8,%9}, {%0,%1,%2,%3};"
        : "+f"(c[0]), "+f"(c[1]), "+f"(c[2]), "+f"(c[3])
        : "r"(a[0]), "r"(a[1]), "r"(a[2]), "r"(a[3]), "r"(b[0]), "r"(b[1]));
}

// ---------------------------------------------------------------------------
// conv: Ah = fp16(A * 8192), pure streaming (1st launch)
// ---------------------------------------------------------------------------
__global__ void __launch_bounds__(256)
conv_kernel(const float *__restrict__ A, __half *__restrict__ Ah) {
    const size_t stride = (size_t)gridDim.x * 256 * 8;
    size_t base = ((size_t)blockIdx.x * 256 + threadIdx.x) * 8;
    const size_t total = (size_t)NNODES * NNODES;
    for (size_t i = base; i < total; i += stride) {
        float4 v0 = *(const float4 *)(A + i);
        float4 v1 = *(const float4 *)(A + i + 4);
        __half2 h[4];
        h[0] = __floats2half2_rn(v0.x * ASCALE, v0.y * ASCALE);
        h[1] = __floats2half2_rn(v0.z * ASCALE, v0.w * ASCALE);
        h[2] = __floats2half2_rn(v1.x * ASCALE, v1.y * ASCALE);
        h[3] = __floats2half2_rn(v1.z * ASCALE, v1.w * ASCALE);
        *(uint4 *)(Ah + i) = *(uint4 *)h;
    }
}

// ---------------------------------------------------------------------------
// y0t: Y0Th[n][i] = fp16(sum_f X[i][f]*W0[f][n])  (2nd launch)
// ---------------------------------------------------------------------------
__global__ void y0t_kernel(const float *__restrict__ X, const float *__restrict__ W0) {
    __shared__ float W0s[FDIM][HDIM];
    __shared__ float ybuf[8][68];
    int lane = threadIdx.x, ty = threadIdx.y;
    int tid = ty * 32 + lane;
#pragma unroll
    for (int j = 0; j < 4; j++) {
        int idx = tid + 256 * j;
        W0s[idx >> 6][idx & 63] = W0[idx];
    }
    __syncthreads();
    int row0 = blockIdx.x * 8;
    int row = row0 + ty;
    float a0 = 0.f, a1 = 0.f;
#pragma unroll
    for (int f = 0; f < FDIM; f++) {
        float xf = X[row * FDIM + f];
        a0 += xf * W0s[f][lane];
        a1 += xf * W0s[f][lane + 32];
    }
    ybuf[ty][lane] = a0;
    ybuf[ty][lane + 32] = a1;
    __syncthreads();
#pragma unroll
    for (int k = 0; k < 2; k++) {
        int v = tid + 256 * k;
        int n = v >> 3, r = v & 7;
        dY0Th[(size_t)n * NNODES + row0 + r] = __float2half_rn(ybuf[r][n]);
    }
}

// ---------------------------------------------------------------------------
// zseg: per-graph block; zero dG row; softmax stats  (3rd launch)
// ---------------------------------------------------------------------------
__global__ void zseg_kernel(const float *__restrict__ X, const int *__restrict__ I) {
    __shared__ int sb[2];
    __shared__ float red[256];
    int g = blockIdx.x, t = threadIdx.x;
    if (t == 0) {
        int a = 0, b = NNODES;
        while (a < b) { int m = (a + b) >> 1; if (I[m] < g) a = m + 1; else b = m; }
        sb[0] = a;
        b = NNODES;
        while (a < b) { int m = (a + b) >> 1; if (I[m] < g + 1) a = m + 1; else b = m; }
        sb[1] = a;
    }
    if (t < HDIM) dG[g * HDIM + t] = 0.f;
    __syncthreads();
    int lo = sb[0], hi = sb[1];

    float zmax = 0.f;
    for (int i = lo + t; i < hi; i += 256)
        zmax = fmaxf(zmax, log1pf(fmaxf(X[i * FDIM], 0.f)));
    red[t] = zmax;
    __syncthreads();
    for (int s = 128; s > 0; s >>= 1) {
        if (t < s) red[t] = fmaxf(red[t], red[t + s]);
        __syncthreads();
    }
    zmax = red[0];
    __syncthreads();

    float se = 0.f, s0 = 0.f, s1 = 0.f, s2 = 0.f;
    for (int i = lo + t; i < hi; i += 256) {
        float z = log1pf(fmaxf(X[i * FDIM], 0.f));
        float w = expf(z - zmax);
        se += w;
        s0 += w * X[i * FDIM + 13];
        s1 += w * X[i * FDIM + 14];
        s2 += w * X[i * FDIM + 15];
    }
    float vals[4] = {se, s0, s1, s2};
#pragma unroll
    for (int q = 0; q < 4; q++) {
        red[t] = vals[q];
        __syncthreads();
        for (int s = 128; s > 0; s >>= 1) {
            if (t < s) red[t] += red[t + s];
            __syncthreads();
        }
        vals[q] = red[0];
        __syncthreads();
    }
    if (t == 0) {
        dZsum[g] = vals[0];
        dZnum[g * 3 + 0] = vals[1];
        dZnum[g * 3 + 1] = vals[2];
        dZnum[g * 3 + 2] = vals[3];
    }
}

// ---------------------------------------------------------------------------
// GEMM (fp16, 512 thr, 16 warps = 4m x 2n x 2kg, in-CTA k-split + reduction)
//   dZP[y] = Ah[:, y*4096...] @ Bh^T   (scaled x8192)
// ---------------------------------------------------------------------------
__global__ void __launch_bounds__(512, 1)
gemm_f16(const __half *__restrict__ Ah, const __half *__restrict__ Bh,
         float *__restrict__ C) {
    extern __shared__ char smc[];
    char *As = smc;                       // [NST2][BM][LDH halfs]
    char *Bs = smc + NST2 * ST2A;         // [NST2][64][LDH halfs]

    const int tid = threadIdx.x;
    const int lane = tid & 31, wid = tid >> 5;
    const int wm = wid & 3;
    const int wn = (wid >> 2) & 1;
    const int kg = wid >> 3;              // k-group 0/1
    const int m0 = blockIdx.x * BM;
    const int kbeg = blockIdx.y * KSPLIT;

    float c[2][4][4] = {};

    // load coords: A has 1024 16B-slots (128 rows x 8 chunks); thread does 2.
    const int arw = tid >> 3;             // 0..63
    const int ach = tid & 7;
    const __half *gA1 = Ah + (size_t)(m0 + arw) * NNODES + kbeg + ach * 8;
    const __half *gA2 = gA1 + (size_t)64 * NNODES;
    const uint32_t sA1 = (uint32_t)__cvta_generic_to_shared(As) + arw * (LDH * 2) + ach * 16;
    const uint32_t sA2 = sA1 + 64 * (LDH * 2);
    const __half *gB = Bh + (size_t)arw * NNODES + kbeg + ach * 8;
    const uint32_t sB = (uint32_t)__cvta_generic_to_shared(Bs) + arw * (LDH * 2) + ach * 16;

    // ldmatrix lane offsets
    const int arow = wm * 32 + (lane & 7) + ((lane >> 3) & 1) * 8;
    const int brow_ = wn * 32 + (lane & 7) + ((lane >> 3) & 1) * 8;
    const int kh = ((lane >> 4) & 1) * 8;

#define G_ISSUE(IT)                                                           \
    do {                                                                      \
        int buf = (IT) % NST2;                                                \
        size_t koff = (size_t)(IT) * BK2;                                     \
        cpa16(sA1 + buf * ST2A, gA1 + koff);                                  \
        cpa16(sA2 + buf * ST2A, gA2 + koff);                                  \
        cpa16(sB + buf * ST2B, gB + koff);                                    \
    } while (0)

#define G_COMPUTE(BUF)                                                        \
    do {                                                                      \
        uint32_t abase = (uint32_t)__cvta_generic_to_shared(As) + (BUF) * ST2A; \
        uint32_t bbase = (uint32_t)__cvta_generic_to_shared(Bs) + (BUF) * ST2B; \
        _Pragma("unroll") for (int kq = 0; kq < 2; kq++) {                    \
            int kb = (kg * 2 + kq) * 16 + kh;                                 \
            uint32_t a[2][4], b[4][2];                                        \
            _Pragma("unroll") for (int mi = 0; mi < 2; mi++) {                \
                uint32_t addr = abase + (arow + mi * 16) * (LDH * 2) + kb * 2; \
                ldsm4(a[mi][0], a[mi][1], a[mi][2], a[mi][3], addr);          \
            }                                                                 \
            _Pragma("unroll") for (int p = 0; p < 2; p++) {                   \
                uint32_t addr = bbase + (brow_ + p * 16) * (LDH * 2) + kb * 2; \
                uint32_t r0, r1, r2, r3;                                      \
                ldsm4(r0, r1, r2, r3, addr);                                  \
                b[p * 2][0] = r0; b[p * 2 + 1][0] = r1;                       \
                b[p * 2][1] = r2; b[p * 2 + 1][1] = r3;                       \
            }                                                                 \
            _Pragma("unroll") for (int mi = 0; mi < 2; mi++)                  \
                _Pragma("unroll") for (int nj = 0; nj < 4; nj++)              \
                    mma_f16(c[mi][nj], a[mi], b[nj]);                         \
        }                                                                     \
    } while (0)

#pragma unroll
    for (int s = 0; s < NST2 - 1; s++) {
        G_ISSUE(s);
        cpa_commit();
    }

    for (int it = 0; it < NIT2; ++it) {
        asm volatile("cp.async.wait_group 2;" ::: "memory");
        __syncthreads();
        if (it + NST2 - 1 < NIT2) G_ISSUE(it + NST2 - 1);
        cpa_commit();
        G_COMPUTE(it % NST2);
    }
    asm volatile("cp.async.wait_group 0;" ::: "memory");
    __syncthreads();

    // in-CTA k-split reduction: kg1 -> smem -> kg0 adds
    float *red = (float *)smc;            // [32][256] = 32 KB
    float *cf = &c[0][0][0];
    const int p_ = wid & 7;
    if (kg == 1) {
#pragma unroll
        for (int j = 0; j < 32; j++) red[j * 256 + p_ * 32 + lane] = cf[j];
    }
    __syncthreads();
    if (kg == 0) {
#pragma unroll
        for (int j = 0; j < 32; j++) cf[j] += red[j * 256 + p_ * 32 + lane];

        float *Cout = C + (size_t)blockIdx.y * NNODES * HDIM;
        int crow = m0 + wm * 32 + (lane >> 2);
        int ccol = wn * 32 + (lane & 3) * 2;
#pragma unroll
        for (int mi = 0; mi < 2; mi++)
#pragma unroll
            for (int nj = 0; nj < 4; nj++) {
                int r = crow + mi * 16, cl = ccol + nj * 8;
                *(float2 *)(Cout + (size_t)r * HDIM + cl) =
                    make_float2(c[mi][nj][0], c[mi][nj][1]);
                *(float2 *)(Cout + (size_t)(r + 8) * HDIM + cl) =
                    make_float2(c[mi][nj][2], c[mi][nj][3]);
            }
    }
#undef G_ISSUE
#undef G_COMPUTE
}

// ---------------------------------------------------------------------------
// mid: h0 = LN(relu(AINV*sum ZP + b0)); store h0 f32; Y1Th fp16
// ---------------------------------------------------------------------------
__global__ void __launch_bounds__(512)
mid_kernel(const float *__restrict__ b0, const float *__restrict__ g0,
           const float *__restrict__ be0, const float *__restrict__ W1) {
    __shared__ float4 W1q[16][64];
    __shared__ __align__(16) float hrow[16][HDIM];
    __shared__ float ybuf[16][68];
    int lane = threadIdx.x, ty = threadIdx.y;
    int tid = ty * 32 + lane;
#pragma unroll
    for (int k = 0; k < 2; k++) {
        int p = tid + 512 * k;
        int t = p >> 6, n = p & 63;
        W1q[t][n] = make_float4(W1[(4 * t + 0) * HDIM + n], W1[(4 * t + 1) * HDIM + n],
                                W1[(4 * t + 2) * HDIM + n], W1[(4 * t + 3) * HDIM + n]);
    }
    __syncthreads();

    int row0 = blockIdx.x * 16;
    int row = row0 + ty;
    float z0 = 0.f, z1 = 0.f;
#pragma unroll
    for (int s = 0; s < NSPLIT; s++) {
        const float *zp = dZP + (size_t)s * NNODES * HDIM + (size_t)row * HDIM;
        z0 += zp[lane];
        z1 += zp[lane + 32];
    }
    z0 = fmaxf(z0 * AINV + b0[lane], 0.f);
    z1 = fmaxf(z1 * AINV + b0[lane + 32], 0.f);
    float s = z0 + z1;
#pragma unroll
    for (int o = 16; o > 0; o >>= 1) s += __shfl_xor_sync(0xffffffffu, s, o);
    float m = s * (1.f / 64.f);
    float d0 = z0 - m, d1 = z1 - m;
    float v = d0 * d0 + d1 * d1;
#pragma unroll
    for (int o = 16; o > 0; o >>= 1) v += __shfl_xor_sync(0xffffffffu, v, o);
    float rs = rsqrtf(v * (1.f / 64.f) + LNEPS);
    float h0a = d0 * rs * g0[lane] + be0[lane];
    float h0b = d1 * rs * g0[lane + 32] + be0[lane + 32];
    dH0[(size_t)row * HDIM + lane] = h0a;
    dH0[(size_t)row * HDIM + lane + 32] = h0b;
    hrow[ty][lane] = h0a;
    hrow[ty][lane + 32] = h0b;
    __syncwarp();
    float a0 = 0.f, a1 = 0.f;
    const float4 *h4 = (const float4 *)&hrow[ty][0];
#pragma unroll
    for (int t = 0; t < 16; t++) {
        float4 h = h4[t];
        float4 wa = W1q[t][lane];
        float4 wb = W1q[t][lane + 32];
        a0 += h.x * wa.x + h.y * wa.y + h.z * wa.z + h.w * wa.w;
        a1 += h.x * wb.x + h.y * wb.y + h.z * wb.z + h.w * wb.w;
    }
    ybuf[ty][lane] = a0;
    ybuf[ty][lane + 32] = a1;
    __syncthreads();
#pragma unroll
    for (int k = 0; k < 2; k++) {
        int p = tid + 512 * k;
        int n = p >> 4, r = p & 15;
        dY1Th[(size_t)n * NNODES + row0 + r] = __float2half_rn(ybuf[r][n]);
    }
}

// ---------------------------------------------------------------------------
// epi2: h = LN(relu(AINV*sum ZP + b1)) + h0; feat/attn matvecs; seg atomics
// ---------------------------------------------------------------------------
__global__ void __launch_bounds__(512)
epi2_kernel(const int *__restrict__ I, const float *__restrict__ b1,
            const float *__restrict__ g1, const float *__restrict__ be1,
            const float *__restrict__ Wf, const float *__restrict__ bf,
            const float *__restrict__ Wa, const float *__restrict__ ba) {
    __shared__ float4 Wfq[16][64];
    __shared__ float4 Waq[16][64];
    __shared__ __align__(16) float hrow[16][HDIM];
    int lane = threadIdx.x, ty = threadIdx.y;
    int tid = ty * 32 + lane;
#pragma unroll
    for (int k = 0; k < 2; k++) {
        int p = tid + 512 * k;
        int t = p >> 6, n = p & 63;
        Wfq[t][n] = make_float4(Wf[(4 * t + 0) * HDIM + n], Wf[(4 * t + 1) * HDIM + n],
                                Wf[(4 * t + 2) * HDIM + n], Wf[(4 * t + 3) * HDIM + n]);
        Waq[t][n] = make_float4(Wa[(4 * t + 0) * HDIM + n], Wa[(4 * t + 1) * HDIM + n],
                                Wa[(4 * t + 2) * HDIM + n], Wa[(4 * t + 3) * HDIM + n]);
    }
    __syncthreads();

    int row = blockIdx.x * 16 + ty;
    float z0 = 0.f, z1 = 0.f;
#pragma unroll
    for (int s = 0; s < NSPLIT; s++) {
        const float *zp = dZP + (size_t)s * NNODES * HDIM + (size_t)row * HDIM;
        z0 += zp[lane];
        z1 += zp[lane + 32];
    }
    z0 = fmaxf(z0 * AINV + b1[lane], 0.f);
    z1 = fmaxf(z1 * AINV + b1[lane + 32], 0.f);
    float s = z0 + z1;
#pragma unroll
    for (int o = 16; o > 0; o >>= 1) s += __shfl_xor_sync(0xffffffffu, s, o);
    float m = s * (1.f / 64.f);
    float d0 = z0 - m, d1 = z1 - m;
    float v = d0 * d0 + d1 * d1;
#pragma unroll
    for (int o = 16; o > 0; o >>= 1) v += __shfl_xor_sync(0xffffffffu, v, o);
    float rs = rsqrtf(v * (1.f / 64.f) + LNEPS);
    float ha = d0 * rs * g1[lane] + be1[lane] + dH0[(size_t)row * HDIM + lane];
    float hb = d1 * rs * g1[lane + 32] + be1[lane + 32] + dH0[(size_t)row * HDIM + lane + 32];
    hrow[ty][lane] = ha;
    hrow[ty][lane + 32] = hb;
    __syncwarp();

    float f0 = bf[lane], f1 = bf[lane + 32];
    float t0 = ba[lane], t1 = ba[lane + 32];
    const float4 *h4 = (const float4 *)&hrow[ty][0];
#pragma unroll
    for (int t = 0; t < 16; t++) {
        float4 h = h4[t];
        float4 fa = Wfq[t][lane];
        float4 fb = Wfq[t][lane + 32];
        float4 aa = Waq[t][lane];
        float4 ab = Waq[t][lane + 32];
        f0 += h.x * fa.x + h.y * fa.y + h.z * fa.z + h.w * fa.w;
        f1 += h.x * fb.x + h.y * fb.y + h.z * fb.z + h.w * fb.w;
        t0 += h.x * aa.x + h.y * aa.y + h.z * aa.z + h.w * aa.w;
        t1 += h.x * ab.x + h.y * ab.y + h.z * ab.z + h.w * ab.w;
    }
    t0 = 1.f / (1.f + expf(-t0));
    t1 = 1.f / (1.f + expf(-t1));
    int g = I[row];
    atomicAdd(&dG[g * HDIM + lane], f0 * t0);
    atomicAdd(&dG[g * HDIM + lane + 32], f1 * t1);
}

// ---------------------------------------------------------------------------
// final: out[g] = [Gacc[g] | bary[g]] @ Wout + bout
// ---------------------------------------------------------------------------
__global__ void final_kernel(const float *__restrict__ Wout,
                             const float *__restrict__ bout, float *__restrict__ out) {
    int g = blockIdx.x * 64 + threadIdx.x;
    if (g >= GSEG) return;
    float a0 = bout[0], a1 = bout[1], a2 = bout[2];
#pragma unroll
    for (int j = 0; j < HDIM; j++) {
        float v = dG[g * HDIM + j];
        a0 += v * Wout[j * 3 + 0];
        a1 += v * Wout[j * 3 + 1];
        a2 += v * Wout[j * 3 + 2];
    }
    float zs = dZsum[g];
    float inv = zs > 0.f ? 1.f / zs : 0.f;
#pragma unroll
    for (int d = 0; d < 3; d++) {
        float b = dZnum[g * 3 + d] * inv;
        a0 += b * Wout[(HDIM + d) * 3 + 0];
        a1 += b * Wout[(HDIM + d) * 3 + 1];
        a2 += b * Wout[(HDIM + d) * 3 + 2];
    }
    out[g * 3 + 0] = a0;
    out[g * 3 + 1] = a1;
    out[g * 3 + 2] = a2;
}

// ---------------------------------------------------------------------------
// launch
// ---------------------------------------------------------------------------
extern "C" void kernel_launch(void *const *d_in, const int *in_sizes, int n_in,
                              void *d_out, int out_size) {
    const float *X = (const float *)d_in[0];
    const float *A = (const float *)d_in[1];
    const int *I = (const int *)d_in[2];
    const float *W0 = (const float *)d_in[3];
    const float *b0 = (const float *)d_in[4];
    const float *g0 = (const float *)d_in[5];
    const float *be0 = (const float *)d_in[6];
    const float *W1 = (const float *)d_in[7];
    const float *b1 = (const float *)d_in[8];
    const float *g1 = (const float *)d_in[9];
    const float *be1 = (const float *)d_in[10];
    const float *Wf = (const float *)d_in[11];
    const float *bf = (const float *)d_in[12];
    const float *Wa = (const float *)d_in[13];
    const float *ba = (const float *)d_in[14];
    const float *Wout = (const float *)d_in[15];
    const float *bout = (const float *)d_in[16];
    float *out = (float *)d_out;

    float *zp;
    __half *ah, *y0th, *y1th;
    cudaGetSymbolAddress((void **)&zp, dZP);
    cudaGetSymbolAddress((void **)&ah, dAh);
    cudaGetSymbolAddress((void **)&y0th, dY0Th);
    cudaGetSymbolAddress((void **)&y1th, dY1Th);

    cudaFuncSetAttribute(gemm_f16, cudaFuncAttributeMaxDynamicSharedMemorySize, SMEM2);

    conv_kernel<<<2048, 256>>>(A, ah);
    y0t_kernel<<<NNODES / 8, dim3(32, 8)>>>(X, W0);
    zseg_kernel<<<GSEG, 256>>>(X, I);
    gemm_f16<<<dim3(NNODES / BM, NSPLIT), 512, SMEM2>>>(ah, y0th, zp);
    mid_kernel<<<NNODES / 16, dim3(32, 16)>>>(b0, g0, be0, W1);
    gemm_f16<<<dim3(NNODES / BM, NSPLIT), 512, SMEM2>>>(ah, y1th, zp);
    epi2_kernel<<<NNODES / 16, dim3(32, 16)>>>(I, b1, g1, be1, Wf, bf, Wa, ba);
    final_kernel<<<(GSEG + 63) / 64, 64>>>(Wout, bout, out);
}